// round 2
// baseline (speedup 1.0000x reference)
#include <cuda_runtime.h>
#include <cstdint>

// Problem constants
#define Bn  16
#define Cc  256
#define HWc 4096
#define Nq  65536          // Bn*HWc
#define Kc  1024
#define ZQ_ELEMS 16777216  // Bn*Cc*HWc

// Tiling for the distance GEMM
#define TM 64     // queries per block
#define TN 128    // codes per k-tile
#define CK 16     // c-chunk staged per step

// smem (floats): zt[256*64] + As[64] + cs[16*128] + rv[64*16] + ri[64*16]
#define SMEM_FLOATS (Cc*TM + TM + CK*TN + TM*16 + TM*16)
#define SMEM_BYTES  (SMEM_FLOATS * 4)

// Scratch (device globals; no allocations allowed)
__device__ float g_cbT[Cc * Kc];    // codebook transposed [C][K]
__device__ float g_bnorm[Kc];       // ||c_k||^2
__device__ int   g_idx[Nq];
__device__ float g_dbest[Nq];

// ---------------------------------------------------------------------------
// Prep: transpose codebook and compute per-code squared norms.
// One block per code k (1024 blocks x 256 threads).
// ---------------------------------------------------------------------------
__global__ void prep_kernel(const float* __restrict__ cb) {
    int k = blockIdx.x;
    int c = threadIdx.x;
    float v = cb[k * Cc + c];
    g_cbT[c * Kc + k] = v;
    __shared__ float sred[256];
    sred[c] = v * v;
    __syncthreads();
    for (int s = 128; s > 0; s >>= 1) {
        if (c < s) sred[c] += sred[c + s];
        __syncthreads();
    }
    if (c == 0) g_bnorm[k] = sred[0];
}

// ---------------------------------------------------------------------------
// Main: per 64-query tile, compute distances to all 1024 codes (fp32),
// mimic reference rounding: t = fl(A + B_k); d = fl(t - 2*dot) via fmaf.
// Argmin with lowest-index tiebreak (matches jnp.argmin first occurrence).
// ---------------------------------------------------------------------------
__global__ void __launch_bounds__(256) vq_main(const float* __restrict__ z) {
    extern __shared__ float sm[];
    float* zt = sm;                 // [Cc][TM]
    float* As = zt + Cc * TM;       // [TM]   ||z||^2 per query
    float* cs = As + TM;            // [CK][TN]
    float* rv = cs + CK * TN;       // [TM][16] reduction values
    int*   ri = (int*)(rv + TM * 16);

    const int tid = threadIdx.x;
    const int tx = tid & 15;        // code lane (16)
    const int ty = tid >> 4;        // query lane (16)
    const int n0 = blockIdx.x * TM;
    const float* zb = z + (size_t)(n0 / HWc) * Cc * HWc + (n0 % HWc);

    // Stage full z tile [256 x 64] (coalesced: 64-float rows)
    #pragma unroll
    for (int m = 0; m < (Cc * TM) / 256; ++m) {
        int flat = tid + 256 * m;
        int c = flat >> 6, q = flat & 63;
        zt[c * TM + q] = zb[(size_t)c * HWc + q];
    }
    __syncthreads();

    // A_q = sum z^2 (sequential fp32, per query)
    if (tid < TM) {
        float a = 0.f;
        #pragma unroll 8
        for (int c = 0; c < Cc; ++c) {
            float v = zt[c * TM + tid];
            a = fmaf(v, v, a);
        }
        As[tid] = a;
    }

    float mv[4]; int mi[4];
    #pragma unroll
    for (int i = 0; i < 4; ++i) { mv[i] = __int_as_float(0x7f800000); mi[i] = 0; }

    for (int kt = 0; kt < Kc / TN; ++kt) {
        float acc[4][8];
        #pragma unroll
        for (int i = 0; i < 4; ++i)
            #pragma unroll
            for (int j = 0; j < 8; ++j) acc[i][j] = 0.f;

        for (int cc = 0; cc < Cc / CK; ++cc) {
            // Stage codebookT chunk [CK x TN] (coalesced: 128-float rows)
            #pragma unroll
            for (int m = 0; m < (CK * TN) / 256; ++m) {
                int flat = tid + 256 * m;
                int r = flat >> 7, col = flat & 127;
                cs[r * TN + col] = g_cbT[(size_t)(cc * CK + r) * Kc + kt * TN + col];
            }
            __syncthreads();

            #pragma unroll
            for (int ck = 0; ck < CK; ++ck) {
                const int c = cc * CK + ck;
                float av[4], bv[8];
                #pragma unroll
                for (int i = 0; i < 4; ++i) av[i] = zt[c * TM + ty + 16 * i];
                #pragma unroll
                for (int j = 0; j < 8; ++j) bv[j] = cs[ck * TN + tx + 16 * j];
                #pragma unroll
                for (int i = 0; i < 4; ++i)
                    #pragma unroll
                    for (int j = 0; j < 8; ++j)
                        acc[i][j] = fmaf(av[i], bv[j], acc[i][j]);
            }
            __syncthreads();
        }

        // Scores + running argmin (k ascending within thread -> strict < keeps lowest k)
        #pragma unroll
        for (int i = 0; i < 4; ++i) {
            float Aq = As[ty + 16 * i];
            #pragma unroll
            for (int j = 0; j < 8; ++j) {
                int k = kt * TN + tx + 16 * j;
                float t = __fadd_rn(Aq, g_bnorm[k]);   // fl(A + B_k)  (reference order)
                float d = fmaf(-2.f, acc[i][j], t);    // fl(t - 2*dot) single rounding
                if (d < mv[i]) { mv[i] = d; mi[i] = k; }
            }
        }
    }

    // Cross-thread reduction over the 16 code-lanes per query
    #pragma unroll
    for (int i = 0; i < 4; ++i) {
        rv[(ty + 16 * i) * 16 + tx] = mv[i];
        ri[(ty + 16 * i) * 16 + tx] = mi[i];
    }
    __syncthreads();
    if (tid < TM) {
        float best = rv[tid * 16];
        int   bk   = ri[tid * 16];
        #pragma unroll
        for (int t = 1; t < 16; ++t) {
            float v = rv[tid * 16 + t];
            int   k2 = ri[tid * 16 + t];
            if (v < best || (v == best && k2 < bk)) { best = v; bk = k2; }
        }
        g_idx[n0 + tid]   = bk;
        g_dbest[n0 + tid] = best;
    }
}

// ---------------------------------------------------------------------------
// Writer: zq_st in NCHW. Replicates the straight-through rounding:
// out = fl(zc + fl(zq - zc))  (NOT bitwise equal to zq).
// One block per (b, c) plane; codebookT row (4KB) stays hot in L1.
// ---------------------------------------------------------------------------
__global__ void write_zq(float* __restrict__ out, const float* __restrict__ z) {
    int p = blockIdx.x;               // b*256 + c
    int b = p >> 8, c = p & 255;
    const float* row  = g_cbT + (size_t)c * Kc;
    const int*   idxp = g_idx + b * HWc;
    const float* zp   = z + (size_t)p * HWc;
    float*       o    = out + (size_t)p * HWc;
    for (int hw = threadIdx.x; hw < HWc; hw += blockDim.x) {
        float zc = zp[hw];
        float zq = row[idxp[hw]];
        o[hw] = __fadd_rn(zc, __fsub_rn(zq, zc));
    }
}

__global__ void write_idx(float* __restrict__ out) {
    int n = blockIdx.x * blockDim.x + threadIdx.x;
    if (n < Nq) out[n] = (float)g_idx[n];
}

// loss = (1 - BETA) * mean((zq - zc)^2); sum of d_best == sum of squared diffs
__global__ void loss_kernel(float* __restrict__ out) {
    __shared__ double sd[256];
    double s = 0.0;
    for (int i = threadIdx.x; i < Nq; i += 256) s += (double)g_dbest[i];
    sd[threadIdx.x] = s;
    __syncthreads();
    for (int r = 128; r > 0; r >>= 1) {
        if (threadIdx.x < r) sd[threadIdx.x] += sd[threadIdx.x + r];
        __syncthreads();
    }
    if (threadIdx.x == 0)
        out[0] = (float)(0.75 * sd[0] / (double)ZQ_ELEMS);
}

// ---------------------------------------------------------------------------
extern "C" void kernel_launch(void* const* d_in, const int* in_sizes, int n_in,
                              void* d_out, int out_size) {
    const float* z  = (const float*)d_in[0];   // [B,C,H,W] fp32
    const float* cb = (const float*)d_in[1];   // [K,C]     fp32
    float* out = (float*)d_out;

    cudaFuncSetAttribute(vq_main, cudaFuncAttributeMaxDynamicSharedMemorySize, SMEM_BYTES);

    prep_kernel<<<Kc, 256>>>(cb);
    vq_main<<<Nq / TM, 256, SMEM_BYTES>>>(z);
    write_zq<<<Bn * Cc, 256>>>(out, z);

    // Output packing: zq [16777216] (+ idx [65536]) (+ loss [1]) — branch on out_size.
    if (out_size >= ZQ_ELEMS + Nq)
        write_idx<<<Nq / 256, 256>>>(out + ZQ_ELEMS);
    if (out_size >= ZQ_ELEMS + Nq + 1)
        loss_kernel<<<1, 256>>>(out + ZQ_ELEMS + Nq);
    else if (out_size == ZQ_ELEMS + 1)
        loss_kernel<<<1, 256>>>(out + ZQ_ELEMS);
}

// round 3
// speedup vs baseline: 1.0347x; 1.0347x over previous
#include <cuda_runtime.h>
#include <cstdint>

// Problem constants
#define Bn  16
#define Cc  256
#define HWc 4096
#define Nq  65536          // Bn*HWc
#define Kc  1024
#define ZQ_ELEMS 16777216  // Bn*Cc*HWc

// Tiling for the distance GEMM
#define TM 64     // queries per block
#define TN 128    // codes per k-tile
#define CK 16     // c-chunk staged per step

// smem (floats): zt[256*64] + As[64] + cs[16*128] + rv[64*16] + ri[64*16]
#define SMEM_FLOATS (Cc*TM + TM + CK*TN + TM*16 + TM*16)
#define SMEM_BYTES  (SMEM_FLOATS * 4)

// Scratch (device globals; no allocations allowed)
__device__ float g_cbT[Cc * Kc];    // codebook transposed [C][K]
__device__ float g_bnorm[Kc];       // ||c_k||^2
__device__ int   g_idx[Nq];
__device__ float g_dbest[Nq];

// ---------------------------------------------------------------------------
// Packed f32x2 helpers (sm_100+). Each lane is an exact fp32 FMA, so results
// are bitwise identical to the scalar FFMA chain with the same order.
// ---------------------------------------------------------------------------
__device__ __forceinline__ unsigned long long f32x2_dup(float v) {
    unsigned long long r;
    asm("mov.b64 %0, {%1, %1};" : "=l"(r) : "f"(v));
    return r;
}
__device__ __forceinline__ unsigned long long ffma2(unsigned long long a,
                                                    unsigned long long b,
                                                    unsigned long long c) {
    unsigned long long d;
    asm("fma.rn.f32x2 %0, %1, %2, %3;" : "=l"(d) : "l"(a), "l"(b), "l"(c));
    return d;
}
__device__ __forceinline__ void f32x2_unpack(unsigned long long v, float& lo, float& hi) {
    asm("mov.b64 {%0, %1}, %2;" : "=f"(lo), "=f"(hi) : "l"(v));
}

// ---------------------------------------------------------------------------
// Prep: transpose codebook and compute per-code squared norms.
// ---------------------------------------------------------------------------
__global__ void prep_kernel(const float* __restrict__ cb) {
    int k = blockIdx.x;
    int c = threadIdx.x;
    float v = cb[k * Cc + c];
    g_cbT[c * Kc + k] = v;
    __shared__ float sred[256];
    sred[c] = v * v;
    __syncthreads();
    for (int s = 128; s > 0; s >>= 1) {
        if (c < s) sred[c] += sred[c + s];
        __syncthreads();
    }
    if (c == 0) g_bnorm[k] = sred[0];
}

// ---------------------------------------------------------------------------
// Main: per 64-query tile, distances to all 1024 codes via packed f32x2 FMAs.
// Thread (tx,ty): queries 4*ty..4*ty+3 (contiguous -> float4 LDS),
//                 codes   8*tx..8*tx+7 (contiguous -> 2x double2 LDS,
//                 which are also the pre-paired f32x2 b-operands).
// Rounding identical to reference path: t = fl(A + B_k); d = fl(t - 2*dot).
// ---------------------------------------------------------------------------
__global__ void __launch_bounds__(256) vq_main(const float* __restrict__ z) {
    extern __shared__ float sm[];
    float* zt = sm;                 // [Cc][TM]
    float* As = zt + Cc * TM;       // [TM]
    float* cs = As + TM;            // [CK][TN]
    float* rv = cs + CK * TN;       // [TM][16]
    int*   ri = (int*)(rv + TM * 16);

    const int tid = threadIdx.x;
    const int tx = tid & 15;        // code lane: codes 8*tx..8*tx+7
    const int ty = tid >> 4;        // query lane: queries 4*ty..4*ty+3
    const int n0 = blockIdx.x * TM;
    const float* zb = z + (size_t)(n0 / HWc) * Cc * HWc + (n0 % HWc);

    // Stage full z tile [256 x 64] (coalesced 64-float rows)
    #pragma unroll
    for (int m = 0; m < (Cc * TM) / 256; ++m) {
        int flat = tid + 256 * m;
        int c = flat >> 6, q = flat & 63;
        zt[c * TM + q] = zb[(size_t)c * HWc + q];
    }
    __syncthreads();

    // A_q = sum z^2 (sequential fp32 per query)
    if (tid < TM) {
        float a = 0.f;
        #pragma unroll 8
        for (int c = 0; c < Cc; ++c) {
            float v = zt[c * TM + tid];
            a = fmaf(v, v, a);
        }
        As[tid] = a;
    }

    float mv[4]; int mi[4];
    #pragma unroll
    for (int i = 0; i < 4; ++i) { mv[i] = __int_as_float(0x7f800000); mi[i] = 0; }

    const float4* zt4 = (const float4*)zt;      // [Cc][16]

    for (int kt = 0; kt < Kc / TN; ++kt) {
        unsigned long long acc2[4][4];           // [query i][code pair p]
        #pragma unroll
        for (int i = 0; i < 4; ++i)
            #pragma unroll
            for (int p = 0; p < 4; ++p) acc2[i][p] = 0ULL;

        for (int cc = 0; cc < Cc / CK; ++cc) {
            // Stage codebookT chunk [CK x TN] (coalesced 128-float rows)
            #pragma unroll
            for (int m = 0; m < (CK * TN) / 256; ++m) {
                int flat = tid + 256 * m;
                int r = flat >> 7, col = flat & 127;
                cs[r * TN + col] = g_cbT[(size_t)(cc * CK + r) * Kc + kt * TN + col];
            }
            __syncthreads();

            #pragma unroll
            for (int ck = 0; ck < CK; ++ck) {
                const int c = cc * CK + ck;
                // a: 4 contiguous queries, one LDS.128
                float4 av4 = zt4[c * 16 + ty];
                unsigned long long ad[4];
                ad[0] = f32x2_dup(av4.x);
                ad[1] = f32x2_dup(av4.y);
                ad[2] = f32x2_dup(av4.z);
                ad[3] = f32x2_dup(av4.w);
                // b: 8 contiguous codes as 4 pre-paired f32x2 operands (2x LDS.128)
                const double2* csd = (const double2*)(cs + ck * TN);
                double2 b0 = csd[2 * tx];
                double2 b1 = csd[2 * tx + 1];
                unsigned long long bp[4];
                bp[0] = __double_as_longlong(b0.x);
                bp[1] = __double_as_longlong(b0.y);
                bp[2] = __double_as_longlong(b1.x);
                bp[3] = __double_as_longlong(b1.y);
                #pragma unroll
                for (int i = 0; i < 4; ++i)
                    #pragma unroll
                    for (int p = 0; p < 4; ++p)
                        acc2[i][p] = ffma2(ad[i], bp[p], acc2[i][p]);
            }
            __syncthreads();
        }

        // Scores + running argmin (ascending k within thread -> strict < keeps lowest k)
        #pragma unroll
        for (int i = 0; i < 4; ++i) {
            float Aq = As[4 * ty + i];
            #pragma unroll
            for (int p = 0; p < 4; ++p) {
                float dlo, dhi;
                f32x2_unpack(acc2[i][p], dlo, dhi);
                int k0 = kt * TN + 8 * tx + 2 * p;
                float t0 = __fadd_rn(Aq, g_bnorm[k0]);
                float d0 = fmaf(-2.f, dlo, t0);
                if (d0 < mv[i]) { mv[i] = d0; mi[i] = k0; }
                float t1 = __fadd_rn(Aq, g_bnorm[k0 + 1]);
                float d1 = fmaf(-2.f, dhi, t1);
                if (d1 < mv[i]) { mv[i] = d1; mi[i] = k0 + 1; }
            }
        }
    }

    // Cross-thread reduction over the 16 code-lanes per query
    #pragma unroll
    for (int i = 0; i < 4; ++i) {
        rv[(4 * ty + i) * 16 + tx] = mv[i];
        ri[(4 * ty + i) * 16 + tx] = mi[i];
    }
    __syncthreads();
    if (tid < TM) {
        float best = rv[tid * 16];
        int   bk   = ri[tid * 16];
        #pragma unroll
        for (int t = 1; t < 16; ++t) {
            float v = rv[tid * 16 + t];
            int   k2 = ri[tid * 16 + t];
            if (v < best || (v == best && k2 < bk)) { best = v; bk = k2; }
        }
        g_idx[n0 + tid]   = bk;
        g_dbest[n0 + tid] = best;
    }
}

// ---------------------------------------------------------------------------
// Writer: zq_st in NCHW. out = fl(zc + fl(zq - zc)) (reference rounding).
// ---------------------------------------------------------------------------
__global__ void write_zq(float* __restrict__ out, const float* __restrict__ z) {
    int p = blockIdx.x;               // b*256 + c
    int b = p >> 8, c = p & 255;
    const float* row  = g_cbT + (size_t)c * Kc;
    const int*   idxp = g_idx + b * HWc;
    const float* zp   = z + (size_t)p * HWc;
    float*       o    = out + (size_t)p * HWc;
    for (int hw = threadIdx.x; hw < HWc; hw += blockDim.x) {
        float zc = zp[hw];
        float zq = row[idxp[hw]];
        o[hw] = __fadd_rn(zc, __fsub_rn(zq, zc));
    }
}

__global__ void write_idx(float* __restrict__ out) {
    int n = blockIdx.x * blockDim.x + threadIdx.x;
    if (n < Nq) out[n] = (float)g_idx[n];
}

// loss = (1 - BETA) * mean((zq - zc)^2)
__global__ void loss_kernel(float* __restrict__ out) {
    __shared__ double sd[256];
    double s = 0.0;
    for (int i = threadIdx.x; i < Nq; i += 256) s += (double)g_dbest[i];
    sd[threadIdx.x] = s;
    __syncthreads();
    for (int r = 128; r > 0; r >>= 1) {
        if (threadIdx.x < r) sd[threadIdx.x] += sd[threadIdx.x + r];
        __syncthreads();
    }
    if (threadIdx.x == 0)
        out[0] = (float)(0.75 * sd[0] / (double)ZQ_ELEMS);
}

// ---------------------------------------------------------------------------
extern "C" void kernel_launch(void* const* d_in, const int* in_sizes, int n_in,
                              void* d_out, int out_size) {
    const float* z  = (const float*)d_in[0];   // [B,C,H,W] fp32
    const float* cb = (const float*)d_in[1];   // [K,C]     fp32
    float* out = (float*)d_out;

    cudaFuncSetAttribute(vq_main, cudaFuncAttributeMaxDynamicSharedMemorySize, SMEM_BYTES);

    prep_kernel<<<Kc, 256>>>(cb);
    vq_main<<<Nq / TM, 256, SMEM_BYTES>>>(z);
    write_zq<<<Bn * Cc, 256>>>(out, z);

    if (out_size >= ZQ_ELEMS + Nq)
        write_idx<<<Nq / 256, 256>>>(out + ZQ_ELEMS);
    if (out_size >= ZQ_ELEMS + Nq + 1)
        loss_kernel<<<1, 256>>>(out + ZQ_ELEMS + Nq);
    else if (out_size == ZQ_ELEMS + 1)
        loss_kernel<<<1, 256>>>(out + ZQ_ELEMS);
}